// round 14
// baseline (speedup 1.0000x reference)
#include <cuda_runtime.h>
#include <math.h>
#include <stdint.h>

#define L_SEQ   2048
#define DMODEL  2048
#define NHEADS  32
#define HDIM    64

// Scratch (allocation-free contract: __device__ globals)
__device__ float g_q[NHEADS * L_SEQ * HDIM];      // [head][token][64]
__device__ float g_k[NHEADS * L_SEQ * HDIM];
__device__ float g_v[NHEADS * L_SEQ * HDIM];
__device__ float g_attn[L_SEQ * DMODEL];          // [token][head*64+d]

// ---------------------------------------------------------------------------
// split-tf32 helpers: x = hi + lo with hi = tf32_rna(x); lo residual is
// exactly representable, then tf32-rounded (residual-of-residual ~2^-22 rel).
// ---------------------------------------------------------------------------
__device__ __forceinline__ void split_tf32(float x, uint32_t& hi, uint32_t& lo) {
    uint32_t h;
    asm("cvt.rna.tf32.f32 %0, %1;" : "=r"(h) : "f"(x));
    float hf = __uint_as_float(h);
    float lf = x - hf;
    asm("cvt.rna.tf32.f32 %0, %1;" : "=r"(lo) : "f"(lf));
    hi = h;
}

__device__ __forceinline__ void mma_tf32(float* d, const uint32_t* a,
                                         uint32_t b0, uint32_t b1) {
    asm volatile(
        "mma.sync.aligned.m16n8k8.row.col.f32.tf32.tf32.f32 "
        "{%0,%1,%2,%3}, {%4,%5,%6,%7}, {%8,%9}, {%0,%1,%2,%3};"
        : "+f"(d[0]), "+f"(d[1]), "+f"(d[2]), "+f"(d[3])
        : "r"(a[0]), "r"(a[1]), "r"(a[2]), "r"(a[3]), "r"(b0), "r"(b1));
}

// ---------------------------------------------------------------------------
// GEMM body: C = A(2048,2048) @ B(2048,2048)^T, row-major A and B.
// 128x128 block tile, BK=8, 256 threads. Producer: double-buffered smem with
// register prefetch. Consumer: split-tf32 mma.sync.m16n8k8 — 8 warps in 4x2,
// warp tile 32x64 (2 m-atoms x 8 n-atoms), 3 mmas per atom-pair
// (AhBh + AhBl + AlBh; AlBl dropped, ~2^-22 rel).
// HEADMAJOR=1: write C[n/64][m][n%64]  (head-major for attention)
// HEADMAJOR=0: write C[m][n]           (token-major)
// ---------------------------------------------------------------------------
template <int HEADMAJOR>
__device__ __forceinline__ void gemm_body(const float* __restrict__ A,
                                          const float* __restrict__ B,
                                          float* __restrict__ C,
                                          int m0, int n0) {
    const int K = DMODEL, N = DMODEL;
    __shared__ float As[2][8][132];   // [buf][k][m], padded stride
    __shared__ float Bs[2][8][132];   // [buf][k][n]

    int tid = threadIdx.x;

    // Producer indexing
    int lr = tid >> 1;            // 0..127 (tile row)
    int lc = (tid & 1) * 4;       // 0 or 4 (k offset)
    const float* Ap = A + (size_t)(m0 + lr) * K + lc;
    const float* Bp = B + (size_t)(n0 + lr) * K + lc;

    // Consumer indexing: warp tile
    int lane = tid & 31, wrp = tid >> 5;
    int wm = (wrp >> 1) * 32;     // 0,32,64,96
    int wn = (wrp & 1) * 64;      // 0,64
    int g = lane >> 2;            // 0..7
    int t = lane & 3;             // 0..3

    float acc[2][8][4];
#pragma unroll
    for (int ma = 0; ma < 2; ma++)
#pragma unroll
        for (int na = 0; na < 8; na++)
#pragma unroll
            for (int r = 0; r < 4; r++) acc[ma][na][r] = 0.f;

    // Prologue: fill buffer 0
    float4 av = *(const float4*)(Ap);
    float4 bv = *(const float4*)(Bp);
    As[0][lc + 0][lr] = av.x; As[0][lc + 1][lr] = av.y;
    As[0][lc + 2][lr] = av.z; As[0][lc + 3][lr] = av.w;
    Bs[0][lc + 0][lr] = bv.x; Bs[0][lc + 1][lr] = bv.y;
    Bs[0][lc + 2][lr] = bv.z; Bs[0][lc + 3][lr] = bv.w;
    __syncthreads();

    int buf = 0;
    for (int k0 = 0; k0 < K; k0 += 8) {
        bool more = (k0 + 8) < K;
        if (more) {
            av = *(const float4*)(Ap + k0 + 8);
            bv = *(const float4*)(Bp + k0 + 8);
        }

        // ---- consume slab [buf]: one k8 mma step ----
        // A fragments (m16n8k8 row): a0..a3 = (g,t),(g+8,t),(g,t+4),(g+8,t+4)
        uint32_t Ah[2][4], Al[2][4];
#pragma unroll
        for (int ma = 0; ma < 2; ma++) {
            int mb = wm + ma * 16;
            split_tf32(As[buf][t    ][mb + g    ], Ah[ma][0], Al[ma][0]);
            split_tf32(As[buf][t    ][mb + g + 8], Ah[ma][1], Al[ma][1]);
            split_tf32(As[buf][t + 4][mb + g    ], Ah[ma][2], Al[ma][2]);
            split_tf32(As[buf][t + 4][mb + g + 8], Ah[ma][3], Al[ma][3]);
        }
        // B fragments (col): b0 = (k=t, n=g), b1 = (k=t+4, n=g); consumed hot
#pragma unroll
        for (int na = 0; na < 8; na++) {
            int nb = wn + na * 8 + g;
            uint32_t bh0, bl0, bh1, bl1;
            split_tf32(Bs[buf][t    ][nb], bh0, bl0);
            split_tf32(Bs[buf][t + 4][nb], bh1, bl1);
#pragma unroll
            for (int ma = 0; ma < 2; ma++) {
                mma_tf32(acc[ma][na], Ah[ma], bh0, bh1);
                mma_tf32(acc[ma][na], Ah[ma], bl0, bl1);
                mma_tf32(acc[ma][na], Al[ma], bh0, bh1);
            }
        }

        if (more) {
            int nb = buf ^ 1;   // write other buffer: no race with current reads
            As[nb][lc + 0][lr] = av.x; As[nb][lc + 1][lr] = av.y;
            As[nb][lc + 2][lr] = av.z; As[nb][lc + 3][lr] = av.w;
            Bs[nb][lc + 0][lr] = bv.x; Bs[nb][lc + 1][lr] = bv.y;
            Bs[nb][lc + 2][lr] = bv.z; Bs[nb][lc + 3][lr] = bv.w;
        }
        __syncthreads();
        buf ^= 1;
    }

    // Epilogue: d-fragment rows {g, g+8}, cols {2t, 2t+1} per atom -> float2
#pragma unroll
    for (int ma = 0; ma < 2; ma++) {
#pragma unroll
        for (int na = 0; na < 8; na++) {
            int m = m0 + wm + ma * 16 + g;
            int n = n0 + wn + na * 8 + t * 2;
            float2 lo = make_float2(acc[ma][na][0], acc[ma][na][1]);
            float2 hi = make_float2(acc[ma][na][2], acc[ma][na][3]);
            if (HEADMAJOR) {
                // 2 consecutive cols stay within one head; 8B-aligned (n even)
                float* base = C + (size_t)(n >> 6) * (L_SEQ * HDIM) + (n & 63);
                *(float2*)(base + (size_t)m * HDIM)       = lo;
                *(float2*)(base + (size_t)(m + 8) * HDIM) = hi;
            } else {
                *(float2*)(C + (size_t)m * N + n)       = lo;
                *(float2*)(C + (size_t)(m + 8) * N + n) = hi;
            }
        }
    }
}

// Fused QKV projection: blockIdx.z selects {Wq->q, Wk->k, Wv->v}.
__global__ __launch_bounds__(256) void gemm_qkv(const float* __restrict__ x,
                                                const float* __restrict__ Wq,
                                                const float* __restrict__ Wk,
                                                const float* __restrict__ Wv,
                                                float* __restrict__ q,
                                                float* __restrict__ k,
                                                float* __restrict__ v) {
    const float* B = (blockIdx.z == 0) ? Wq : (blockIdx.z == 1) ? Wk : Wv;
    float*       C = (blockIdx.z == 0) ? q  : (blockIdx.z == 1) ? k  : v;
    gemm_body<1>(x, B, C, blockIdx.y * 128, blockIdx.x * 128);
}

// Output projection: attn @ Wo^T, token-major.
__global__ __launch_bounds__(256) void gemm_out(const float* __restrict__ A,
                                                const float* __restrict__ B,
                                                float* __restrict__ C) {
    gemm_body<0>(A, B, C, blockIdx.y * 128, blockIdx.x * 128);
}

// ---------------------------------------------------------------------------
// RoPE (non-interleaved output, matching reference):
//   out[i]    = x[2i]*cos - x[2i+1]*sin   (i in [0,32))
//   out[32+i] = x[2i]*sin + x[2i+1]*cos
// ---------------------------------------------------------------------------
__global__ void rope_kernel(float* __restrict__ q, float* __restrict__ k) {
    __shared__ float row[64];
    int token = blockIdx.x, head = blockIdx.y;
    float* p = (blockIdx.z == 0 ? q : k) + ((size_t)head * L_SEQ + token) * HDIM;
    int t = threadIdx.x;
    row[t] = p[t];
    __syncthreads();
    if (t < 32) {
        // accurate powf: fast-math inv_freq error -> ~2e-4 rad at pos~2048
        float inv = powf(10000.0f, -(float)t * (1.0f / 32.0f));
        float ang = (float)token * inv;
        float s, c;
        sincosf(ang, &s, &c);
        float x1 = row[2 * t], x2 = row[2 * t + 1];
        p[t]      = x1 * c - x2 * s;
        p[t + 32] = x1 * s + x2 * c;
    }
}

// ---------------------------------------------------------------------------
// Flash attention: 1 thread = 1 query row. q[64], o[64] in registers.
// K/V tiles of 64 rows in smem (broadcast reads). Online softmax with
// rare-rescale branch. grid = (L/128, NHEADS), 128 threads.
// ---------------------------------------------------------------------------
__global__ __launch_bounds__(128) void flash_attn(const float* __restrict__ gq,
                                                  const float* __restrict__ gk,
                                                  const float* __restrict__ gv,
                                                  const int* __restrict__ mask,
                                                  float* __restrict__ out) {
    __shared__ float Ks[64][64];
    __shared__ float Vs[64][64];
    __shared__ int ms[64];

    int head = blockIdx.y;
    int qrow = blockIdx.x * 128 + threadIdx.x;
    int tid = threadIdx.x;

    const float* qp = gq + ((size_t)head * L_SEQ + qrow) * HDIM;
    float q[64], o[64];
#pragma unroll
    for (int d = 0; d < 64; d++) { q[d] = qp[d]; o[d] = 0.f; }

    float m = -1e30f, l = 0.f;

    for (int k0 = 0; k0 < L_SEQ; k0 += 64) {
        const float* kp = gk + ((size_t)head * L_SEQ + k0) * HDIM;
        const float* vp = gv + ((size_t)head * L_SEQ + k0) * HDIM;
#pragma unroll 4
        for (int i = tid; i < 64 * 16; i += 128) {
            int r = i >> 4, c = i & 15;
            ((float4*)Ks[r])[c] = ((const float4*)(kp + r * HDIM))[c];
            ((float4*)Vs[r])[c] = ((const float4*)(vp + r * HDIM))[c];
        }
        if (tid < 64) ms[tid] = mask[k0 + tid];
        __syncthreads();

        for (int j = 0; j < 64; j++) {
            float s = 0.f;
#pragma unroll
            for (int d = 0; d < 64; d++) s = fmaf(q[d], Ks[j][d], s);
            s *= 0.125f;                      // 1/sqrt(64)
            if (ms[j] == 0) s = -1e9f;

            if (s > m) {
                float alpha = __expf(m - s);
                m = s;
                l = l * alpha + 1.f;
#pragma unroll
                for (int d = 0; d < 64; d++) o[d] = fmaf(o[d], alpha, Vs[j][d]);
            } else {
                float p = __expf(s - m);
                l += p;
#pragma unroll
                for (int d = 0; d < 64; d++) o[d] = fmaf(p, Vs[j][d], o[d]);
            }
        }
        __syncthreads();
    }

    float inv = 1.f / l;
    float* op = out + (size_t)qrow * DMODEL + head * HDIM;
#pragma unroll
    for (int d = 0; d < 64; d++) op[d] = o[d] * inv;
}

// ---------------------------------------------------------------------------
extern "C" void kernel_launch(void* const* d_in, const int* in_sizes, int n_in,
                              void* d_out, int out_size) {
    const float* x    = (const float*)d_in[0];
    const int*   mask = (const int*)  d_in[1];
    const float* Wq   = (const float*)d_in[2];
    const float* Wk   = (const float*)d_in[3];
    const float* Wv   = (const float*)d_in[4];
    const float* Wo   = (const float*)d_in[5];
    float* out = (float*)d_out;

    float *q, *k, *v, *attn;
    cudaGetSymbolAddress((void**)&q, g_q);
    cudaGetSymbolAddress((void**)&k, g_k);
    cudaGetSymbolAddress((void**)&v, g_v);
    cudaGetSymbolAddress((void**)&attn, g_attn);

    dim3 gqkv(DMODEL / 128, L_SEQ / 128, 3);
    gemm_qkv<<<gqkv, 256>>>(x, Wq, Wk, Wv, q, k, v);

    rope_kernel<<<dim3(L_SEQ, NHEADS, 2), 64>>>(q, k);

    flash_attn<<<dim3(L_SEQ / 128, NHEADS), 128>>>(q, k, v, mask, attn);

    dim3 gg(DMODEL / 128, L_SEQ / 128);
    gemm_out<<<gg, 256>>>(attn, Wo, out);
}

// round 15
// speedup vs baseline: 1.4917x; 1.4917x over previous
#include <cuda_runtime.h>
#include <math.h>
#include <stdint.h>

#define L_SEQ   2048
#define DMODEL  2048
#define NHEADS  32
#define HDIM    64

// Scratch (allocation-free contract: __device__ globals)
__device__ float g_q[NHEADS * L_SEQ * HDIM];      // [head][token][64]
__device__ float g_k[NHEADS * L_SEQ * HDIM];
__device__ float g_v[NHEADS * L_SEQ * HDIM];
__device__ float g_attn[L_SEQ * DMODEL];          // [token][head*64+d]

// ---------------------------------------------------------------------------
// tf32 helpers
// ---------------------------------------------------------------------------
__device__ __forceinline__ void split_tf32(float x, uint32_t& hi, uint32_t& lo) {
    uint32_t h;
    asm("cvt.rna.tf32.f32 %0, %1;" : "=r"(h) : "f"(x));
    float hf = __uint_as_float(h);
    float lf = x - hf;
    asm("cvt.rna.tf32.f32 %0, %1;" : "=r"(lo) : "f"(lf));
    hi = h;
}

__device__ __forceinline__ float tf32r(float x) {
    uint32_t h;
    asm("cvt.rna.tf32.f32 %0, %1;" : "=r"(h) : "f"(x));
    return __uint_as_float(h);
}

__device__ __forceinline__ void mma_tf32(float* d, const uint32_t* a,
                                         uint32_t b0, uint32_t b1) {
    asm volatile(
        "mma.sync.aligned.m16n8k8.row.col.f32.tf32.tf32.f32 "
        "{%0,%1,%2,%3}, {%4,%5,%6,%7}, {%8,%9}, {%0,%1,%2,%3};"
        : "+f"(d[0]), "+f"(d[1]), "+f"(d[2]), "+f"(d[3])
        : "r"(a[0]), "r"(a[1]), "r"(a[2]), "r"(a[3]), "r"(b0), "r"(b1));
}

// ---------------------------------------------------------------------------
// GEMM body: unchanged from the R14-validated kernel (split-tf32 mma).
// ---------------------------------------------------------------------------
template <int HEADMAJOR>
__device__ __forceinline__ void gemm_body(const float* __restrict__ A,
                                          const float* __restrict__ B,
                                          float* __restrict__ C,
                                          int m0, int n0) {
    const int K = DMODEL, N = DMODEL;
    __shared__ float As[2][8][132];
    __shared__ float Bs[2][8][132];

    int tid = threadIdx.x;
    int lr = tid >> 1;
    int lc = (tid & 1) * 4;
    const float* Ap = A + (size_t)(m0 + lr) * K + lc;
    const float* Bp = B + (size_t)(n0 + lr) * K + lc;

    int lane = tid & 31, wrp = tid >> 5;
    int wm = (wrp >> 1) * 32;
    int wn = (wrp & 1) * 64;
    int g = lane >> 2;
    int t = lane & 3;

    float acc[2][8][4];
#pragma unroll
    for (int ma = 0; ma < 2; ma++)
#pragma unroll
        for (int na = 0; na < 8; na++)
#pragma unroll
            for (int r = 0; r < 4; r++) acc[ma][na][r] = 0.f;

    float4 av = *(const float4*)(Ap);
    float4 bv = *(const float4*)(Bp);
    As[0][lc + 0][lr] = av.x; As[0][lc + 1][lr] = av.y;
    As[0][lc + 2][lr] = av.z; As[0][lc + 3][lr] = av.w;
    Bs[0][lc + 0][lr] = bv.x; Bs[0][lc + 1][lr] = bv.y;
    Bs[0][lc + 2][lr] = bv.z; Bs[0][lc + 3][lr] = bv.w;
    __syncthreads();

    int buf = 0;
    for (int k0 = 0; k0 < K; k0 += 8) {
        bool more = (k0 + 8) < K;
        if (more) {
            av = *(const float4*)(Ap + k0 + 8);
            bv = *(const float4*)(Bp + k0 + 8);
        }

        uint32_t Ah[2][4], Al[2][4];
#pragma unroll
        for (int ma = 0; ma < 2; ma++) {
            int mb = wm + ma * 16;
            split_tf32(As[buf][t    ][mb + g    ], Ah[ma][0], Al[ma][0]);
            split_tf32(As[buf][t    ][mb + g + 8], Ah[ma][1], Al[ma][1]);
            split_tf32(As[buf][t + 4][mb + g    ], Ah[ma][2], Al[ma][2]);
            split_tf32(As[buf][t + 4][mb + g + 8], Ah[ma][3], Al[ma][3]);
        }
#pragma unroll
        for (int na = 0; na < 8; na++) {
            int nb = wn + na * 8 + g;
            uint32_t bh0, bl0, bh1, bl1;
            split_tf32(Bs[buf][t    ][nb], bh0, bl0);
            split_tf32(Bs[buf][t + 4][nb], bh1, bl1);
#pragma unroll
            for (int ma = 0; ma < 2; ma++) {
                mma_tf32(acc[ma][na], Ah[ma], bh0, bh1);
                mma_tf32(acc[ma][na], Ah[ma], bl0, bl1);
                mma_tf32(acc[ma][na], Al[ma], bh0, bh1);
            }
        }

        if (more) {
            int nb = buf ^ 1;
            As[nb][lc + 0][lr] = av.x; As[nb][lc + 1][lr] = av.y;
            As[nb][lc + 2][lr] = av.z; As[nb][lc + 3][lr] = av.w;
            Bs[nb][lc + 0][lr] = bv.x; Bs[nb][lc + 1][lr] = bv.y;
            Bs[nb][lc + 2][lr] = bv.z; Bs[nb][lc + 3][lr] = bv.w;
        }
        __syncthreads();
        buf ^= 1;
    }

#pragma unroll
    for (int ma = 0; ma < 2; ma++) {
#pragma unroll
        for (int na = 0; na < 8; na++) {
            int m = m0 + wm + ma * 16 + g;
            int n = n0 + wn + na * 8 + t * 2;
            float2 lo = make_float2(acc[ma][na][0], acc[ma][na][1]);
            float2 hi = make_float2(acc[ma][na][2], acc[ma][na][3]);
            if (HEADMAJOR) {
                float* base = C + (size_t)(n >> 6) * (L_SEQ * HDIM) + (n & 63);
                *(float2*)(base + (size_t)m * HDIM)       = lo;
                *(float2*)(base + (size_t)(m + 8) * HDIM) = hi;
            } else {
                *(float2*)(C + (size_t)m * N + n)       = lo;
                *(float2*)(C + (size_t)(m + 8) * N + n) = hi;
            }
        }
    }
}

__global__ __launch_bounds__(256) void gemm_qkv(const float* __restrict__ x,
                                                const float* __restrict__ Wq,
                                                const float* __restrict__ Wk,
                                                const float* __restrict__ Wv,
                                                float* __restrict__ q,
                                                float* __restrict__ k,
                                                float* __restrict__ v) {
    const float* B = (blockIdx.z == 0) ? Wq : (blockIdx.z == 1) ? Wk : Wv;
    float*       C = (blockIdx.z == 0) ? q  : (blockIdx.z == 1) ? k  : v;
    gemm_body<1>(x, B, C, blockIdx.y * 128, blockIdx.x * 128);
}

__global__ __launch_bounds__(256) void gemm_out(const float* __restrict__ A,
                                                const float* __restrict__ B,
                                                float* __restrict__ C) {
    gemm_body<0>(A, B, C, blockIdx.y * 128, blockIdx.x * 128);
}

// ---------------------------------------------------------------------------
// RoPE (unchanged, validated R14)
// ---------------------------------------------------------------------------
__global__ void rope_kernel(float* __restrict__ q, float* __restrict__ k) {
    __shared__ float row[64];
    int token = blockIdx.x, head = blockIdx.y;
    float* p = (blockIdx.z == 0 ? q : k) + ((size_t)head * L_SEQ + token) * HDIM;
    int t = threadIdx.x;
    row[t] = p[t];
    __syncthreads();
    if (t < 32) {
        float inv = powf(10000.0f, -(float)t * (1.0f / 32.0f));
        float ang = (float)token * inv;
        float s, c;
        sincosf(ang, &s, &c);
        float x1 = row[2 * t], x2 = row[2 * t + 1];
        p[t]      = x1 * c - x2 * s;
        p[t + 32] = x1 * s + x2 * c;
    }
}

// ---------------------------------------------------------------------------
// Tensor-core flash attention.
// CTA = (q-tile of 64 rows) x (1 head). 4 warps, warp w owns q-rows
// [16w, 16w+16). 32 K-tiles of 64 keys.
//  QK^T: Q split-tf32 in regs (2 mma), K single-tf32 in smem.
//  Online softmax on d-fragments (rows g/g+8 per lane, quad shfl reduce).
//  PV: P tf32-rounded staged via smem (d-frag -> a-frag transposition),
//      V single-tf32 (1 mma).
// KP buffer overlaid: K tile during QK, Q staging before loop, P during PV.
// Pad stride 68: bank = (4g+t) mod 32 unique for all fragment patterns.
// ---------------------------------------------------------------------------
__global__ __launch_bounds__(128) void flash_attn_mma(const float* __restrict__ gq,
                                                      const float* __restrict__ gk,
                                                      const float* __restrict__ gv,
                                                      const int* __restrict__ mask,
                                                      float* __restrict__ out) {
    __shared__ float KP[64][68];   // Q stage -> K tile -> P stage (overlaid)
    __shared__ float Vs[64][68];   // V tile (tf32-rounded)
    __shared__ int ms[64];

    int head = blockIdx.y, qt = blockIdx.x;
    int tid = threadIdx.x, w = tid >> 5, lane = tid & 31;
    int g = lane >> 2, t = lane & 3;

    // ---- stage Q tile, then per-warp fragment conversion (once per CTA) ----
    const float* qbase = gq + ((size_t)head * L_SEQ + qt * 64) * HDIM;
    for (int i = tid; i < 64 * 16; i += 128) {
        int r = i >> 4, c = i & 15;
        *(float4*)&KP[r][c * 4] = ((const float4*)(qbase + r * HDIM))[c];
    }
    __syncthreads();

    uint32_t Qh[8][4], Ql[8][4];   // a-frags: rows {g,g+8}, cols {t,t+4} per kstep
#pragma unroll
    for (int ks = 0; ks < 8; ks++) {
        split_tf32(KP[16 * w + g    ][ks * 8 + t    ], Qh[ks][0], Ql[ks][0]);
        split_tf32(KP[16 * w + g + 8][ks * 8 + t    ], Qh[ks][1], Ql[ks][1]);
        split_tf32(KP[16 * w + g    ][ks * 8 + t + 4], Qh[ks][2], Ql[ks][2]);
        split_tf32(KP[16 * w + g + 8][ks * 8 + t + 4], Qh[ks][3], Ql[ks][3]);
    }

    float o[8][4];
#pragma unroll
    for (int nd = 0; nd < 8; nd++)
#pragma unroll
        for (int r = 0; r < 4; r++) o[nd][r] = 0.f;
    float m_g = -1e30f, m_h = -1e30f, l_g = 0.f, l_h = 0.f;

    for (int kt = 0; kt < 32; kt++) {
        __syncthreads();   // prior-phase reads of KP/Vs complete (Q frags on iter 0)

        // ---- load K,V tiles (tf32-round at producer: single cvt per element) ----
        const float* kp = gk + ((size_t)head * L_SEQ + kt * 64) * HDIM;
        const float* vp = gv + ((size_t)head * L_SEQ + kt * 64) * HDIM;
        for (int i = tid; i < 64 * 16; i += 128) {
            int r = i >> 4, c = i & 15;
            float4 kv = ((const float4*)(kp + r * HDIM))[c];
            float4 vv = ((const float4*)(vp + r * HDIM))[c];
            kv.x = tf32r(kv.x); kv.y = tf32r(kv.y); kv.z = tf32r(kv.z); kv.w = tf32r(kv.w);
            vv.x = tf32r(vv.x); vv.y = tf32r(vv.y); vv.z = tf32r(vv.z); vv.w = tf32r(vv.w);
            *(float4*)&KP[r][c * 4] = kv;
            *(float4*)&Vs[r][c * 4] = vv;
        }
        if (tid < 64) ms[tid] = mask[kt * 64 + tid];
        __syncthreads();

        // ---- S = Q K^T  (b0=(k=t,n=g) -> K[na*8+g][ks*8+t]) ----
        float s[8][4];
#pragma unroll
        for (int na = 0; na < 8; na++)
#pragma unroll
            for (int r = 0; r < 4; r++) s[na][r] = 0.f;
#pragma unroll
        for (int ks = 0; ks < 8; ks++) {
#pragma unroll
            for (int na = 0; na < 8; na++) {
                uint32_t b0 = __float_as_uint(KP[na * 8 + g][ks * 8 + t    ]);
                uint32_t b1 = __float_as_uint(KP[na * 8 + g][ks * 8 + t + 4]);
                mma_tf32(s[na], Qh[ks], b0, b1);
                mma_tf32(s[na], Ql[ks], b0, b1);
            }
        }
        __syncthreads();   // all warps done reading K before P overwrites KP

        // ---- scale + mask + online softmax ----
        float mt_g = -1e30f, mt_h = -1e30f;
#pragma unroll
        for (int na = 0; na < 8; na++) {
            int c0 = na * 8 + 2 * t, c1 = c0 + 1;
            bool k0m = (ms[c0] == 0), k1m = (ms[c1] == 0);
            s[na][0] = k0m ? -1e9f : s[na][0] * 0.125f;
            s[na][1] = k1m ? -1e9f : s[na][1] * 0.125f;
            s[na][2] = k0m ? -1e9f : s[na][2] * 0.125f;
            s[na][3] = k1m ? -1e9f : s[na][3] * 0.125f;
            mt_g = fmaxf(mt_g, fmaxf(s[na][0], s[na][1]));
            mt_h = fmaxf(mt_h, fmaxf(s[na][2], s[na][3]));
        }
        mt_g = fmaxf(mt_g, __shfl_xor_sync(0xffffffffu, mt_g, 1));
        mt_g = fmaxf(mt_g, __shfl_xor_sync(0xffffffffu, mt_g, 2));
        mt_h = fmaxf(mt_h, __shfl_xor_sync(0xffffffffu, mt_h, 1));
        mt_h = fmaxf(mt_h, __shfl_xor_sync(0xffffffffu, mt_h, 2));

        float mn_g = fmaxf(m_g, mt_g), mn_h = fmaxf(m_h, mt_h);
        float a_g = __expf(m_g - mn_g), a_h = __expf(m_h - mn_h);
        m_g = mn_g; m_h = mn_h;

        float ps_g = 0.f, ps_h = 0.f;
#pragma unroll
        for (int na = 0; na < 8; na++) {
            int c0 = na * 8 + 2 * t, c1 = c0 + 1;
            float p0 = __expf(s[na][0] - mn_g);
            float p1 = __expf(s[na][1] - mn_g);
            float p2 = __expf(s[na][2] - mn_h);
            float p3 = __expf(s[na][3] - mn_h);
            ps_g += p0 + p1;
            ps_h += p2 + p3;
            KP[16 * w + g    ][c0] = tf32r(p0);
            KP[16 * w + g    ][c1] = tf32r(p1);
            KP[16 * w + g + 8][c0] = tf32r(p2);
            KP[16 * w + g + 8][c1] = tf32r(p3);
        }
        ps_g += __shfl_xor_sync(0xffffffffu, ps_g, 1);
        ps_g += __shfl_xor_sync(0xffffffffu, ps_g, 2);
        ps_h += __shfl_xor_sync(0xffffffffu, ps_h, 1);
        ps_h += __shfl_xor_sync(0xffffffffu, ps_h, 2);
        l_g = l_g * a_g + ps_g;
        l_h = l_h * a_h + ps_h;

#pragma unroll
        for (int nd = 0; nd < 8; nd++) {
            o[nd][0] *= a_g; o[nd][1] *= a_g;
            o[nd][2] *= a_h; o[nd][3] *= a_h;
        }
        __syncwarp();   // warp-local P region visible across lanes

        // ---- O += P V  (a-frags from KP own rows; b0=(k=t,n=g) -> V[ks*8+t][nd*8+g]) ----
#pragma unroll
        for (int ks = 0; ks < 8; ks++) {
            uint32_t a[4];
            a[0] = __float_as_uint(KP[16 * w + g    ][ks * 8 + t    ]);
            a[1] = __float_as_uint(KP[16 * w + g + 8][ks * 8 + t    ]);
            a[2] = __float_as_uint(KP[16 * w + g    ][ks * 8 + t + 4]);
            a[3] = __float_as_uint(KP[16 * w + g + 8][ks * 8 + t + 4]);
#pragma unroll
            for (int nd = 0; nd < 8; nd++) {
                uint32_t b0 = __float_as_uint(Vs[ks * 8 + t    ][nd * 8 + g]);
                uint32_t b1 = __float_as_uint(Vs[ks * 8 + t + 4][nd * 8 + g]);
                mma_tf32(o[nd], a, b0, b1);
            }
        }
    }

    // ---- normalize + write [token][head*64+d] ----
    float il_g = 1.f / l_g, il_h = 1.f / l_h;
    int row = qt * 64 + 16 * w + g;
#pragma unroll
    for (int nd = 0; nd < 8; nd++) {
        int col = head * HDIM + nd * 8 + 2 * t;
        float2 lo = make_float2(o[nd][0] * il_g, o[nd][1] * il_g);
        float2 hi = make_float2(o[nd][2] * il_h, o[nd][3] * il_h);
        *(float2*)(out + (size_t)row * DMODEL + col)       = lo;
        *(float2*)(out + (size_t)(row + 8) * DMODEL + col) = hi;
    }
}

// ---------------------------------------------------------------------------
extern "C" void kernel_launch(void* const* d_in, const int* in_sizes, int n_in,
                              void* d_out, int out_size) {
    const float* x    = (const float*)d_in[0];
    const int*   mask = (const int*)  d_in[1];
    const float* Wq   = (const float*)d_in[2];
    const float* Wk   = (const float*)d_in[3];
    const float* Wv   = (const float*)d_in[4];
    const float* Wo   = (const float*)d_in[5];
    float* out = (float*)d_out;

    float *q, *k, *v, *attn;
    cudaGetSymbolAddress((void**)&q, g_q);
    cudaGetSymbolAddress((void**)&k, g_k);
    cudaGetSymbolAddress((void**)&v, g_v);
    cudaGetSymbolAddress((void**)&attn, g_attn);

    dim3 gqkv(DMODEL / 128, L_SEQ / 128, 3);
    gemm_qkv<<<gqkv, 256>>>(x, Wq, Wk, Wv, q, k, v);

    rope_kernel<<<dim3(L_SEQ, NHEADS, 2), 64>>>(q, k);

    flash_attn_mma<<<dim3(L_SEQ / 64, NHEADS), 128>>>(q, k, v, mask, attn);

    dim3 gg(DMODEL / 128, L_SEQ / 128);
    gemm_out<<<gg, 256>>>(attn, Wo, out);
}